// round 16
// baseline (speedup 1.0000x reference)
#include <cuda_runtime.h>
#include <cuda_fp16.h>
#include <math.h>

// Fixed problem shapes
#define FCN   16
#define WT    593
#define H_    152
#define W_    272
#define HW_   41344
#define B_    4
#define M_    32
#define BM_   128
#define EPS_  1.0e-4f
#define NT16  2584            // HW_/16 pixel tiles
#define NQUAD 646             // groups of 4 tiles (64 px)
#define GRIDX 20
#define TOTALBLK (GRIDX * BM_)

// Scratch (allocations forbidden)
__device__ double   g_neg_acc;
__device__ double   g_pos_acc;
__device__ unsigned g_done;
__device__ uint4    g_featX[(long long)B_ * NT16 * 32];   // fragment-ordered features
__device__ uint4    g_coordA[NT16 * 32];                  // pre-splatted (xg,xg),(xg8,xg8),(y,y),0

__device__ __forceinline__ unsigned pack_h2(float lo, float hi) {
    unsigned d;
    asm("cvt.rn.f16x2.f32 %0, %1, %2;" : "=r"(d) : "f"(hi), "f"(lo));
    return d;
}
__device__ __forceinline__ unsigned relu_h2(unsigned u) {
    __half2 h = *reinterpret_cast<__half2*>(&u);
    h = __hmax2(h, __half2(__float2half_rn(0.f), __float2half_rn(0.f)));
    return *reinterpret_cast<unsigned*>(&h);
}
__device__ __forceinline__ __half2 asH2(unsigned u) {
    return *reinterpret_cast<const __half2*>(&u);
}
__device__ __forceinline__ unsigned asU(__half2 h) {
    return *reinterpret_cast<const unsigned*>(&h);
}

// ---- pre-pass: build m16k16 A fragments + splatted coord regs; resets accumulators ----
__global__ __launch_bounds__(128)
void feat_frag_kernel(const float* __restrict__ sf) {
    if (blockIdx.x == 0 && blockIdx.y == 0 && threadIdx.x == 0) {
        g_neg_acc = 0.0;
        g_pos_acc = 0.0;
        g_done    = 0u;
    }
    __shared__ float sm[4][16][16];   // [w][c][px]
    const int w    = threadIdx.x >> 5;
    const int t    = threadIdx.x & 31;
    const int tile = blockIdx.x * 4 + w;
    const int b    = blockIdx.y;
    const int base = tile * 16;

    const int c  = t >> 1;
    const int h8 = (t & 1) * 8;
    const float* src = sf + ((long long)b * FCN + c) * HW_ + base + h8;
    const float4 v0 = *(const float4*)src;
    const float4 v1 = *(const float4*)(src + 4);
    sm[w][c][h8 + 0] = v0.x; sm[w][c][h8 + 1] = v0.y;
    sm[w][c][h8 + 2] = v0.z; sm[w][c][h8 + 3] = v0.w;
    sm[w][c][h8 + 4] = v1.x; sm[w][c][h8 + 5] = v1.y;
    sm[w][c][h8 + 6] = v1.z; sm[w][c][h8 + 7] = v1.w;
    __syncwarp();

    const int g  = t >> 2;
    const int tq = t & 3;
    const int k0 = 2 * tq, k1 = k0 + 1, k2 = k0 + 8, k3 = k2 + 1;

    __half2 a0 = __floats2half2_rn(sm[w][k0][g],     sm[w][k1][g]);
    __half2 a1 = __floats2half2_rn(sm[w][k0][g + 8], sm[w][k1][g + 8]);
    __half2 a2 = __floats2half2_rn(sm[w][k2][g],     sm[w][k3][g]);
    __half2 a3 = __floats2half2_rn(sm[w][k2][g + 8], sm[w][k3][g + 8]);

    uint4 o;
    o.x = *(unsigned*)&a0; o.y = *(unsigned*)&a1;
    o.z = *(unsigned*)&a2; o.w = *(unsigned*)&a3;
    g_featX[((long long)b * NT16 + tile) * 32 + t] = o;

    // pre-splatted coord registers: (xg,xg), (xg8,xg8), (y,y). Exact in fp16.
    if (b == 0) {
        const float inv128 = 1.0f / 128.0f;
        const float xg = (float)((tile % 17) * 16 + g) * inv128;
        const float yv = (float)(tile / 17) * inv128;
        uint4 ca;
        ca.x = pack_h2(xg, xg);
        ca.y = pack_h2(xg + 8.0f * inv128, xg + 8.0f * inv128);
        ca.z = pack_h2(yv, yv);
        ca.w = 0u;
        g_coordA[tile * 32 + t] = ca;
    }
}

// fp16-output HMMA: D, C are 2x f16x2 regs
__device__ __forceinline__ void mma16816h(
    unsigned& d0, unsigned& d1,
    unsigned a0, unsigned a1, unsigned a2, unsigned a3,
    unsigned b0, unsigned b1,
    unsigned c0, unsigned c1)
{
    asm("mma.sync.aligned.m16n8k16.row.col.f16.f16.f16.f16 "
        "{%0,%1}, {%2,%3,%4,%5}, {%6,%7}, {%8,%9};"
        : "=r"(d0), "=r"(d1)
        : "r"(a0), "r"(a1), "r"(a2), "r"(a3), "r"(b0), "r"(b1),
          "r"(c0), "r"(c1));
}

__global__ __launch_bounds__(128, 8)
void sch_loss_main(const float* __restrict__ conv_weight,
                   const float* __restrict__ mask,
                   const int*   __restrict__ pre_ind,
                   const float* __restrict__ target,
                   const int*   __restrict__ ind,
                   float* __restrict__ out)
{
    __shared__ __align__(4) __half w1h[256];   // [o*16 + c], c<16
    __shared__ __align__(4) __half w2h[256];   // [o*16 + c]
    __shared__ float b1f[16], b2f[16], w3f[16], wxf[16], wyf[16];
    __shared__ float b1c[16];                  // bias with coord offset folded in
    __shared__ float b3s;
    __shared__ float sred[4];
    __shared__ int   s_last;

    const int bm   = blockIdx.y;
    const int b    = bm >> 5;
    const int tid  = threadIdx.x;
    const int wid  = tid >> 5;
    const int lane = tid & 31;
    const int pi   = pre_ind[bm];

    const float x0 = (float)(pi % W_);
    const float y0 = (float)pi / (float)W_;     // float division, matching reference
    const float inv128 = 1.0f / 128.0f;

    // ---- prologue: gather + route 593 weights ----
    for (int idx = tid; idx < WT; idx += 128) {
        const float v = conv_weight[((long long)b * WT + idx) * HW_ + pi];
        if (idx < 288) {
            const int o = idx / 18, c = idx % 18;
            if      (c < 16)  w1h[o * 16 + c] = __float2half_rn(v);
            else if (c == 16) wxf[o] = v;
            else              wyf[o] = v;
        } else if (idx < 304) b1f[idx - 288] = v;
        else if (idx < 560)   w2h[idx - 304] = __float2half_rn(v);
        else if (idx < 576)   b2f[idx - 560] = v;
        else if (idx < 592)   w3f[idx - 576] = v;
        else                  b3s = v;
    }
    __syncthreads();
    if (tid < 16)
        b1c[tid] = b1f[tid] - (wxf[tid] * x0 + wyf[tid] * y0) * inv128;
    __syncthreads();

    const int g  = lane >> 2;
    const int tq = lane & 3;
    const int k0 = 2 * tq, k2 = k0 + 8;
    const int k1 = k0 + 1, k3 = k2 + 1;

    const unsigned b1a0 = *(const unsigned*)&w1h[g * 16 + k0];
    const unsigned b1a1 = *(const unsigned*)&w1h[g * 16 + k2];
    const unsigned b1b0 = *(const unsigned*)&w1h[(g + 8) * 16 + k0];
    const unsigned b1b1 = *(const unsigned*)&w1h[(g + 8) * 16 + k2];
    const unsigned b2a0 = *(const unsigned*)&w2h[g * 16 + k0];
    const unsigned b2a1 = *(const unsigned*)&w2h[g * 16 + k2];
    const unsigned b2b0 = *(const unsigned*)&w2h[(g + 8) * 16 + k0];
    const unsigned b2b1 = *(const unsigned*)&w2h[(g + 8) * 16 + k2];
    const unsigned b30 = pack_h2(w3f[k0], w3f[k1]);
    const unsigned b31 = pack_h2(w3f[k2], w3f[k3]);

    // coord weights at this thread's D columns (for C-operand FMA)
    const __half2 cwx01 = asH2(pack_h2(wxf[k0], wxf[k1]));
    const __half2 cwx23 = asH2(pack_h2(wxf[k2], wxf[k3]));
    const __half2 cwy01 = asH2(pack_h2(wyf[k0], wyf[k1]));
    const __half2 cwy23 = asH2(pack_h2(wyf[k2], wyf[k3]));

    const __half2 cA1 = asH2(pack_h2(b1c[k0], b1c[k1]));
    const __half2 cB1 = asH2(pack_h2(b1c[k2], b1c[k3]));
    const unsigned cA2 = pack_h2(b2f[k0], b2f[k1]);
    const unsigned cB2 = pack_h2(b2f[k2], b2f[k3]);
    const float b3v = b3s;

    const float* __restrict__ tg = target + (long long)bm * HW_;
    const char*  __restrict__ fxb = (const char*)(g_featX + (long long)b * NT16 * 32)
                                    + (unsigned)lane * 16u;
    const char*  __restrict__ cab = (const char*)g_coordA + (unsigned)lane * 16u;
    const int   posind = ind[bm];
    const float mval   = mask[bm];

    float negAcc = 0.0f;

    for (int q = blockIdx.x * 4 + wid; q < NQUAD; q += GRIDX * 4) {
        const int tile0 = q * 4;

        // ---- batched independent loads (32-bit offsets) ----
        const unsigned off0 = (unsigned)tile0 * 512u;
        const uint4 af0 = *(const uint4*)(fxb + off0);
        const uint4 af1 = *(const uint4*)(fxb + off0 + 512u);
        const uint4 af2 = *(const uint4*)(fxb + off0 + 1024u);
        const uint4 af3 = *(const uint4*)(fxb + off0 + 1536u);
        const uint4 ca0 = *(const uint4*)(cab + off0);
        const uint4 ca1 = *(const uint4*)(cab + off0 + 512u);
        const uint4 ca2 = *(const uint4*)(cab + off0 + 1024u);
        const uint4 ca3 = *(const uint4*)(cab + off0 + 1536u);
        const int  pxlo = tile0 * 16 + tq * 16 + g;
        const float tlo = tg[pxlo];
        const float thi = tg[pxlo + 8];

        unsigned zsel0 = 0u, zsel1 = 0u;

        #pragma unroll
        for (int t = 0; t < 4; ++t) {
            const uint4 af = (t == 0) ? af0 : (t == 1) ? af1 : (t == 2) ? af2 : af3;
            const uint4 ca = (t == 0) ? ca0 : (t == 1) ? ca1 : (t == 2) ? ca2 : ca3;

            // C-operand coord fold: C(r,n) = b1c_n + wx_n*x_r/128 + wy_n*y/128
            // splatted regs come straight from the load — zero PRMT
            const __half2 hxg  = asH2(ca.x);
            const __half2 hxg8 = asH2(ca.y);
            const __half2 hy   = asH2(ca.z);
            const __half2 ty01 = __hfma2(cwy01, hy, cA1);
            const __half2 ty23 = __hfma2(cwy23, hy, cB1);
            const unsigned cd0 = asU(__hfma2(cwx01, hxg,  ty01));
            const unsigned cd1 = asU(__hfma2(cwx01, hxg8, ty01));
            const unsigned ce0 = asU(__hfma2(cwx23, hxg,  ty23));
            const unsigned ce1 = asU(__hfma2(cwx23, hxg8, ty23));

            unsigned d0, d1, e0, e1;
            // layer 1 (fp16 out), coord+bias carried in C
            mma16816h(d0, d1, af.x, af.y, af.z, af.w, b1a0, b1a1, cd0, cd1);
            mma16816h(e0, e1, af.x, af.y, af.z, af.w, b1b0, b1b1, ce0, ce1);

            const unsigned A0 = relu_h2(d0);
            const unsigned A1 = relu_h2(d1);
            const unsigned A2 = relu_h2(e0);
            const unsigned A3 = relu_h2(e1);

            // layer 2 (fp16 out)
            mma16816h(d0, d1, A0, A1, A2, A3, b2a0, b2a1, cA2, cA2);
            mma16816h(e0, e1, A0, A1, A2, A3, b2b0, b2b1, cB2, cB2);

            const unsigned C0 = relu_h2(d0);
            const unsigned C1 = relu_h2(d1);
            const unsigned C2 = relu_h2(e0);
            const unsigned C3 = relu_h2(e1);

            // layer 3: w3 broadcast in all columns -> z in every D half
            unsigned z0, z1;
            mma16816h(z0, z1, C0, C1, C2, C3, b30, b31, 0u, 0u);
            if (t == tq) { zsel0 = z0; zsel1 = z1; }
        }

        const float zvlo = __low2float(asH2(zsel0));
        const float zvhi = __low2float(asH2(zsel1));

        // ---- epilogue: 2 pixels per thread ----
        {
            const float zv = zvlo + b3v;
            float hm = 1.0f / (1.0f + __expf(-zv));
            hm = fminf(fmaxf(hm, EPS_), 1.0f - EPS_);
            float qv = 1.0f - tlo;
            qv = qv * qv; qv = qv * qv;
            negAcc += __logf(1.0f - hm) * hm * hm * qv;
            if (pxlo == posind) {
                const float om = 1.0f - hm;
                atomicAdd(&g_pos_acc, (double)(__logf(hm) * om * om * mval));
            }
        }
        {
            const float zv = zvhi + b3v;
            float hm = 1.0f / (1.0f + __expf(-zv));
            hm = fminf(fmaxf(hm, EPS_), 1.0f - EPS_);
            float qv = 1.0f - thi;
            qv = qv * qv; qv = qv * qv;
            negAcc += __logf(1.0f - hm) * hm * hm * qv;
            if (pxlo + 8 == posind) {
                const float om = 1.0f - hm;
                atomicAdd(&g_pos_acc, (double)(__logf(hm) * om * om * mval));
            }
        }
    }

    // ---- block reduction, one double atomic per block ----
    #pragma unroll
    for (int off = 16; off > 0; off >>= 1)
        negAcc += __shfl_down_sync(0xFFFFFFFFu, negAcc, off);
    if (lane == 0) sred[wid] = negAcc;
    __syncthreads();
    if (tid < 32) {
        float v = (tid < 4) ? sred[tid] : 0.0f;
        #pragma unroll
        for (int off = 2; off > 0; off >>= 1)
            v += __shfl_down_sync(0xFFFFFFFFu, v, off);
        if (tid == 0) atomicAdd(&g_neg_acc, (double)v);
    }

    // ---- last-block finalize ----
    if (tid == 0) {
        __threadfence();
        const unsigned c = atomicAdd(&g_done, 1u);
        s_last = (c == TOTALBLK - 1u) ? 1 : 0;
    }
    __syncthreads();
    if (s_last && tid < 32) {
        float np = 0.0f;
        for (int i = tid; i < BM_; i += 32) np += mask[i];
        #pragma unroll
        for (int off = 16; off > 0; off >>= 1)
            np += __shfl_down_sync(0xFFFFFFFFu, np, off);
        if (tid == 0) {
            const double neg = *(volatile double*)&g_neg_acc;
            const double pos = *(volatile double*)&g_pos_acc;
            double loss;
            if (np == 0.0f) loss = -neg;
            else            loss = -(pos + neg) / (double)fmaxf(np, 1.0f);
            out[0] = (float)loss;
        }
    }
}

extern "C" void kernel_launch(void* const* d_in, const int* in_sizes, int n_in,
                              void* d_out, int out_size)
{
    const float* sch_feat    = (const float*)d_in[0];
    const float* conv_weight = (const float*)d_in[1];
    const float* mask        = (const float*)d_in[2];
    const int*   pre_ind     = (const int*)  d_in[3];
    const float* target      = (const float*)d_in[4];
    const int*   ind         = (const int*)  d_in[5];
    float* out = (float*)d_out;

    feat_frag_kernel<<<dim3(NT16 / 4, B_), 128>>>(sch_feat);

    dim3 grid(GRIDX, BM_);
    sch_loss_main<<<grid, 128>>>(conv_weight, mask, pre_ind, target, ind, out);
}

// round 17
// speedup vs baseline: 1.0106x; 1.0106x over previous
#include <cuda_runtime.h>
#include <cuda_fp16.h>
#include <math.h>

// Fixed problem shapes
#define FCN   16
#define WT    593
#define H_    152
#define W_    272
#define HW_   41344
#define B_    4
#define M_    32
#define BM_   128
#define EPS_  1.0e-4f
#define NT16  2584            // HW_/16 pixel tiles
#define NQUAD 646             // groups of 4 tiles (64 px)
#define GRIDX 20
#define TOTALBLK (GRIDX * BM_)

// Scratch (allocations forbidden)
__device__ double   g_neg_acc;
__device__ double   g_pos_acc;
__device__ unsigned g_done;
__device__ uint4    g_featX[(long long)B_ * NT16 * 32];   // fragment-ordered features
__device__ uint2    g_coordA[NT16 * 32];                  // splats: (xg,xg),(y,y)

__device__ __forceinline__ unsigned pack_h2(float lo, float hi) {
    unsigned d;
    asm("cvt.rn.f16x2.f32 %0, %1, %2;" : "=r"(d) : "f"(hi), "f"(lo));
    return d;
}
__device__ __forceinline__ unsigned relu_h2(unsigned u) {
    __half2 h = *reinterpret_cast<__half2*>(&u);
    h = __hmax2(h, __half2(__float2half_rn(0.f), __float2half_rn(0.f)));
    return *reinterpret_cast<unsigned*>(&h);
}
__device__ __forceinline__ __half2 asH2(unsigned u) {
    return *reinterpret_cast<const __half2*>(&u);
}
__device__ __forceinline__ unsigned asU(__half2 h) {
    return *reinterpret_cast<const unsigned*>(&h);
}

// ---- pre-pass: build m16k16 A fragments + coord splats; resets accumulators ----
__global__ __launch_bounds__(128)
void feat_frag_kernel(const float* __restrict__ sf) {
    if (blockIdx.x == 0 && blockIdx.y == 0 && threadIdx.x == 0) {
        g_neg_acc = 0.0;
        g_pos_acc = 0.0;
        g_done    = 0u;
    }
    __shared__ float sm[4][16][16];   // [w][c][px]
    const int w    = threadIdx.x >> 5;
    const int t    = threadIdx.x & 31;
    const int tile = blockIdx.x * 4 + w;
    const int b    = blockIdx.y;
    const int base = tile * 16;

    const int c  = t >> 1;
    const int h8 = (t & 1) * 8;
    const float* src = sf + ((long long)b * FCN + c) * HW_ + base + h8;
    const float4 v0 = *(const float4*)src;
    const float4 v1 = *(const float4*)(src + 4);
    sm[w][c][h8 + 0] = v0.x; sm[w][c][h8 + 1] = v0.y;
    sm[w][c][h8 + 2] = v0.z; sm[w][c][h8 + 3] = v0.w;
    sm[w][c][h8 + 4] = v1.x; sm[w][c][h8 + 5] = v1.y;
    sm[w][c][h8 + 6] = v1.z; sm[w][c][h8 + 7] = v1.w;
    __syncwarp();

    const int g  = t >> 2;
    const int tq = t & 3;
    const int k0 = 2 * tq, k1 = k0 + 1, k2 = k0 + 8, k3 = k2 + 1;

    __half2 a0 = __floats2half2_rn(sm[w][k0][g],     sm[w][k1][g]);
    __half2 a1 = __floats2half2_rn(sm[w][k0][g + 8], sm[w][k1][g + 8]);
    __half2 a2 = __floats2half2_rn(sm[w][k2][g],     sm[w][k3][g]);
    __half2 a3 = __floats2half2_rn(sm[w][k2][g + 8], sm[w][k3][g + 8]);

    uint4 o;
    o.x = *(unsigned*)&a0; o.y = *(unsigned*)&a1;
    o.z = *(unsigned*)&a2; o.w = *(unsigned*)&a3;
    g_featX[((long long)b * NT16 + tile) * 32 + t] = o;

    // coord splats: (xg,xg), (y,y). Exact in fp16 (ints <= 271 over 2^7).
    if (b == 0) {
        const float inv128 = 1.0f / 128.0f;
        const float xg = (float)((tile % 17) * 16 + g) * inv128;
        const float yv = (float)(tile / 17) * inv128;
        uint2 ca;
        ca.x = pack_h2(xg, xg);
        ca.y = pack_h2(yv, yv);
        g_coordA[tile * 32 + t] = ca;
    }
}

// fp16-output HMMA: D, C are 2x f16x2 regs
__device__ __forceinline__ void mma16816h(
    unsigned& d0, unsigned& d1,
    unsigned a0, unsigned a1, unsigned a2, unsigned a3,
    unsigned b0, unsigned b1,
    unsigned c0, unsigned c1)
{
    asm("mma.sync.aligned.m16n8k16.row.col.f16.f16.f16.f16 "
        "{%0,%1}, {%2,%3,%4,%5}, {%6,%7}, {%8,%9};"
        : "=r"(d0), "=r"(d1)
        : "r"(a0), "r"(a1), "r"(a2), "r"(a3), "r"(b0), "r"(b1),
          "r"(c0), "r"(c1));
}

__global__ __launch_bounds__(128, 6)
void sch_loss_main(const float* __restrict__ conv_weight,
                   const float* __restrict__ mask,
                   const int*   __restrict__ pre_ind,
                   const float* __restrict__ target,
                   const int*   __restrict__ ind,
                   float* __restrict__ out)
{
    __shared__ __align__(4) __half w1h[256];   // [o*16 + c], c<16
    __shared__ __align__(4) __half w2h[256];   // [o*16 + c]
    __shared__ float b1f[16], b2f[16], w3f[16], wxf[16], wyf[16];
    __shared__ float b1c[16];                  // bias with coord offset folded in
    __shared__ float b3s;
    __shared__ float sred[4];
    __shared__ int   s_last;

    const int bm   = blockIdx.y;
    const int b    = bm >> 5;
    const int tid  = threadIdx.x;
    const int wid  = tid >> 5;
    const int lane = tid & 31;
    const int pi   = pre_ind[bm];

    const float x0 = (float)(pi % W_);
    const float y0 = (float)pi / (float)W_;     // float division, matching reference
    const float inv128 = 1.0f / 128.0f;

    // ---- prologue: gather + route 593 weights ----
    for (int idx = tid; idx < WT; idx += 128) {
        const float v = conv_weight[((long long)b * WT + idx) * HW_ + pi];
        if (idx < 288) {
            const int o = idx / 18, c = idx % 18;
            if      (c < 16)  w1h[o * 16 + c] = __float2half_rn(v);
            else if (c == 16) wxf[o] = v;
            else              wyf[o] = v;
        } else if (idx < 304) b1f[idx - 288] = v;
        else if (idx < 560)   w2h[idx - 304] = __float2half_rn(v);
        else if (idx < 576)   b2f[idx - 560] = v;
        else if (idx < 592)   w3f[idx - 576] = v;
        else                  b3s = v;
    }
    __syncthreads();
    if (tid < 16)
        b1c[tid] = b1f[tid] - (wxf[tid] * x0 + wyf[tid] * y0) * inv128;
    __syncthreads();

    const int g  = lane >> 2;
    const int tq = lane & 3;
    const int k0 = 2 * tq, k2 = k0 + 8;
    const int k1 = k0 + 1, k3 = k2 + 1;

    const unsigned b1a0 = *(const unsigned*)&w1h[g * 16 + k0];
    const unsigned b1a1 = *(const unsigned*)&w1h[g * 16 + k2];
    const unsigned b1b0 = *(const unsigned*)&w1h[(g + 8) * 16 + k0];
    const unsigned b1b1 = *(const unsigned*)&w1h[(g + 8) * 16 + k2];
    const unsigned b2a0 = *(const unsigned*)&w2h[g * 16 + k0];
    const unsigned b2a1 = *(const unsigned*)&w2h[g * 16 + k2];
    const unsigned b2b0 = *(const unsigned*)&w2h[(g + 8) * 16 + k0];
    const unsigned b2b1 = *(const unsigned*)&w2h[(g + 8) * 16 + k2];
    const unsigned b30 = pack_h2(w3f[k0], w3f[k1]);
    const unsigned b31 = pack_h2(w3f[k2], w3f[k3]);

    // coord weights at this thread's D columns (for C-operand FMA)
    const __half2 cwx01 = asH2(pack_h2(wxf[k0], wxf[k1]));
    const __half2 cwx23 = asH2(pack_h2(wxf[k2], wxf[k3]));
    const __half2 cwy01 = asH2(pack_h2(wyf[k0], wyf[k1]));
    const __half2 cwy23 = asH2(pack_h2(wyf[k2], wyf[k3]));

    const __half2 cA1 = asH2(pack_h2(b1c[k0], b1c[k1]));
    const __half2 cB1 = asH2(pack_h2(b1c[k2], b1c[k3]));
    const unsigned cA2 = pack_h2(b2f[k0], b2f[k1]);
    const unsigned cB2 = pack_h2(b2f[k2], b2f[k3]);
    const float b3v = b3s;
    const __half2 dx8 = asH2(pack_h2(0.0625f, 0.0625f));   // 8/128, exact

    const float* __restrict__ tg = target + (long long)bm * HW_;
    const char*  __restrict__ fxb = (const char*)(g_featX + (long long)b * NT16 * 32)
                                    + (unsigned)lane * 16u;
    const char*  __restrict__ cab = (const char*)g_coordA + (unsigned)lane * 8u;
    const int   posind = ind[bm];
    const float mval   = mask[bm];

    float negAcc = 0.0f;

    for (int q = blockIdx.x * 4 + wid; q < NQUAD; q += GRIDX * 4) {
        const int tile0 = q * 4;

        // ---- batched independent loads (32-bit offsets; MLP = 10) ----
        const unsigned off0 = (unsigned)tile0 * 512u;
        const uint4 af0 = *(const uint4*)(fxb + off0);
        const uint4 af1 = *(const uint4*)(fxb + off0 + 512u);
        const uint4 af2 = *(const uint4*)(fxb + off0 + 1024u);
        const uint4 af3 = *(const uint4*)(fxb + off0 + 1536u);
        const unsigned coff = (unsigned)tile0 * 256u;
        const uint2 ca0 = *(const uint2*)(cab + coff);
        const uint2 ca1 = *(const uint2*)(cab + coff + 256u);
        const uint2 ca2 = *(const uint2*)(cab + coff + 512u);
        const uint2 ca3 = *(const uint2*)(cab + coff + 768u);
        const int  pxlo = tile0 * 16 + tq * 16 + g;
        const float tlo = tg[pxlo];
        const float thi = tg[pxlo + 8];

        unsigned zsel0 = 0u, zsel1 = 0u;

        #pragma unroll
        for (int t = 0; t < 4; ++t) {
            const uint4 af = (t == 0) ? af0 : (t == 1) ? af1 : (t == 2) ? af2 : af3;
            const uint2 ca = (t == 0) ? ca0 : (t == 1) ? ca1 : (t == 2) ? ca2 : ca3;

            // C-operand coord fold: C(r,n) = b1c_n + wx_n*x_r/128 + wy_n*y/128
            // splats load-ready; xg8 derived with one exact HADD2
            const __half2 hxg  = asH2(ca.x);
            const __half2 hy   = asH2(ca.y);
            const __half2 hxg8 = __hadd2(hxg, dx8);
            const __half2 ty01 = __hfma2(cwy01, hy, cA1);
            const __half2 ty23 = __hfma2(cwy23, hy, cB1);
            const unsigned cd0 = asU(__hfma2(cwx01, hxg,  ty01));
            const unsigned cd1 = asU(__hfma2(cwx01, hxg8, ty01));
            const unsigned ce0 = asU(__hfma2(cwx23, hxg,  ty23));
            const unsigned ce1 = asU(__hfma2(cwx23, hxg8, ty23));

            unsigned d0, d1, e0, e1;
            // layer 1 (fp16 out), coord+bias carried in C
            mma16816h(d0, d1, af.x, af.y, af.z, af.w, b1a0, b1a1, cd0, cd1);
            mma16816h(e0, e1, af.x, af.y, af.z, af.w, b1b0, b1b1, ce0, ce1);

            const unsigned A0 = relu_h2(d0);
            const unsigned A1 = relu_h2(d1);
            const unsigned A2 = relu_h2(e0);
            const unsigned A3 = relu_h2(e1);

            // layer 2 (fp16 out)
            mma16816h(d0, d1, A0, A1, A2, A3, b2a0, b2a1, cA2, cA2);
            mma16816h(e0, e1, A0, A1, A2, A3, b2b0, b2b1, cB2, cB2);

            const unsigned C0 = relu_h2(d0);
            const unsigned C1 = relu_h2(d1);
            const unsigned C2 = relu_h2(e0);
            const unsigned C3 = relu_h2(e1);

            // layer 3: w3 broadcast in all columns -> z in every D half
            unsigned z0, z1;
            mma16816h(z0, z1, C0, C1, C2, C3, b30, b31, 0u, 0u);
            if (t == tq) { zsel0 = z0; zsel1 = z1; }
        }

        const float zvlo = __low2float(asH2(zsel0));
        const float zvhi = __low2float(asH2(zsel1));

        // ---- epilogue: 2 pixels per thread ----
        {
            const float zv = zvlo + b3v;
            float hm = 1.0f / (1.0f + __expf(-zv));
            hm = fminf(fmaxf(hm, EPS_), 1.0f - EPS_);
            float qv = 1.0f - tlo;
            qv = qv * qv; qv = qv * qv;
            negAcc += __logf(1.0f - hm) * hm * hm * qv;
            if (pxlo == posind) {
                const float om = 1.0f - hm;
                atomicAdd(&g_pos_acc, (double)(__logf(hm) * om * om * mval));
            }
        }
        {
            const float zv = zvhi + b3v;
            float hm = 1.0f / (1.0f + __expf(-zv));
            hm = fminf(fmaxf(hm, EPS_), 1.0f - EPS_);
            float qv = 1.0f - thi;
            qv = qv * qv; qv = qv * qv;
            negAcc += __logf(1.0f - hm) * hm * hm * qv;
            if (pxlo + 8 == posind) {
                const float om = 1.0f - hm;
                atomicAdd(&g_pos_acc, (double)(__logf(hm) * om * om * mval));
            }
        }
    }

    // ---- block reduction, one double atomic per block ----
    #pragma unroll
    for (int off = 16; off > 0; off >>= 1)
        negAcc += __shfl_down_sync(0xFFFFFFFFu, negAcc, off);
    if (lane == 0) sred[wid] = negAcc;
    __syncthreads();
    if (tid < 32) {
        float v = (tid < 4) ? sred[tid] : 0.0f;
        #pragma unroll
        for (int off = 2; off > 0; off >>= 1)
            v += __shfl_down_sync(0xFFFFFFFFu, v, off);
        if (tid == 0) atomicAdd(&g_neg_acc, (double)v);
    }

    // ---- last-block finalize ----
    if (tid == 0) {
        __threadfence();
        const unsigned c = atomicAdd(&g_done, 1u);
        s_last = (c == TOTALBLK - 1u) ? 1 : 0;
    }
    __syncthreads();
    if (s_last && tid < 32) {
        float np = 0.0f;
        for (int i = tid; i < BM_; i += 32) np += mask[i];
        #pragma unroll
        for (int off = 16; off > 0; off >>= 1)
            np += __shfl_down_sync(0xFFFFFFFFu, np, off);
        if (tid == 0) {
            const double neg = *(volatile double*)&g_neg_acc;
            const double pos = *(volatile double*)&g_pos_acc;
            double loss;
            if (np == 0.0f) loss = -neg;
            else            loss = -(pos + neg) / (double)fmaxf(np, 1.0f);
            out[0] = (float)loss;
        }
    }
}

extern "C" void kernel_launch(void* const* d_in, const int* in_sizes, int n_in,
                              void* d_out, int out_size)
{
    const float* sch_feat    = (const float*)d_in[0];
    const float* conv_weight = (const float*)d_in[1];
    const float* mask        = (const float*)d_in[2];
    const int*   pre_ind     = (const int*)  d_in[3];
    const float* target      = (const float*)d_in[4];
    const int*   ind         = (const int*)  d_in[5];
    float* out = (float*)d_out;

    feat_frag_kernel<<<dim3(NT16 / 4, B_), 128>>>(sch_feat);

    dim3 grid(GRIDX, BM_);
    sch_loss_main<<<grid, 128>>>(conv_weight, mask, pre_ind, target, ind, out);
}